// round 6
// baseline (speedup 1.0000x reference)
#include <cuda_runtime.h>

// Problem constants
#define B_    32
#define TH    256
#define TQ    64
#define DIN   256
#define DD    256   // internal dim
#define KD    256   // reduction dim of projections

// Scratch (allocation-free rule: __device__ globals)
__device__ float g_kpT[B_ * DD * TH];  // 8 MB, TRANSPOSED: [b][d][t]
__device__ float g_qp [B_ * TQ * DD];  // 2 MB, [b*TQ+q][d]

__device__ __forceinline__ float tanh_fast(float x) {
    float y;
    asm("tanh.approx.f32 %0, %1;" : "=f"(y) : "f"(x));
    return y;
}

// ---------------------------------------------------------------------------
// Kernel 1: combined projection GEMM (unchanged — at FFMA+LDS roofline).
//   g_kpT[b][d][t] = sum_k inputs[(b*TH+t), k] * w1[d, k]   (transposed store)
//   g_qp[(b*TQ+q), d] = sum_k state[(b*TQ+q), k] * w2[d, k]
// ---------------------------------------------------------------------------
__global__ __launch_bounds__(256) void proj_gemm(
    const float* __restrict__ inputs, const float* __restrict__ state,
    const float* __restrict__ w1, const float* __restrict__ w2)
{
    const int PAD = 68;
    __shared__ __align__(16) float As[16 * PAD];
    __shared__ __align__(16) float Bs[16 * PAD];

    const bool is_kp = (blockIdx.x < 128);
    const float* A;
    const float* W;
    int m0;
    if (is_kp) { A = inputs; W = w1; m0 = blockIdx.x * 64; }
    else       { A = state;  W = w2; m0 = (blockIdx.x - 128) * 64; }

    const int n0  = blockIdx.y * 64;
    const int tid = threadIdx.x;
    const int ty  = tid & 15;
    const int tx  = tid >> 4;
    const int lrow = tid >> 2;
    const int lk4  = (tid & 3) << 2;

    float acc[4][4];
#pragma unroll
    for (int i = 0; i < 4; i++)
#pragma unroll
        for (int j = 0; j < 4; j++) acc[i][j] = 0.f;

    for (int kt = 0; kt < KD; kt += 16) {
        float4 av = *(const float4*)&A[(size_t)(m0 + lrow) * KD + kt + lk4];
        float4 wv = *(const float4*)&W[(size_t)(n0 + lrow) * KD + kt + lk4];
        __syncthreads();
        As[(lk4 + 0) * PAD + lrow] = av.x;
        As[(lk4 + 1) * PAD + lrow] = av.y;
        As[(lk4 + 2) * PAD + lrow] = av.z;
        As[(lk4 + 3) * PAD + lrow] = av.w;
        Bs[(lk4 + 0) * PAD + lrow] = wv.x;
        Bs[(lk4 + 1) * PAD + lrow] = wv.y;
        Bs[(lk4 + 2) * PAD + lrow] = wv.z;
        Bs[(lk4 + 3) * PAD + lrow] = wv.w;
        __syncthreads();
#pragma unroll
        for (int kk = 0; kk < 16; kk++) {
            float4 aa = *(const float4*)&As[kk * PAD + ty * 4];
            float4 bb = *(const float4*)&Bs[kk * PAD + tx * 4];
            float ar[4] = {aa.x, aa.y, aa.z, aa.w};
            float br[4] = {bb.x, bb.y, bb.z, bb.w};
#pragma unroll
            for (int i = 0; i < 4; i++)
#pragma unroll
                for (int j = 0; j < 4; j++)
                    acc[i][j] = fmaf(ar[i], br[j], acc[i][j]);
        }
    }

    if (is_kp) {
        const int b  = m0 >> 8;
        const int t0 = m0 & 255;
#pragma unroll
        for (int j = 0; j < 4; j++) {
            float4 o = make_float4(acc[0][j], acc[1][j], acc[2][j], acc[3][j]);
            *(float4*)&g_kpT[(size_t)(b * DD + n0 + tx * 4 + j) * TH + t0 + ty * 4] = o;
        }
    } else {
#pragma unroll
        for (int i = 0; i < 4; i++) {
            float4 o = make_float4(acc[i][0], acc[i][1], acc[i][2], acc[i][3]);
            *(float4*)&g_qp[(size_t)(m0 + ty * 4 + i) * DD + n0 + tx * 4] = o;
        }
    }
}

// ---------------------------------------------------------------------------
// Kernel 2: scores + softmax + context, fused. grid = (TQ/4, B) = 512 blocks,
// 256 threads, 4 queries per block. Double-buffered SMEM staging with LDG
// prefetch (1 barrier per chunk). Thread owns t (score) / i (context).
// sqp packed as float4 per d; v hoisted to regs per chunk; softmax kept
// unnormalized (contexts scaled by 1/sum at the end).
// ---------------------------------------------------------------------------
__global__ __launch_bounds__(256) void attn_kernel(
    const float* __restrict__ keys, const float* __restrict__ v,
    const float* __restrict__ qp_g, float* __restrict__ out)
{
    __shared__ __align__(16) float stage[2][16][260];  // 33 KB ping-pong
    __shared__ __align__(16) float sc[4][256];         // scores -> exp(scores)
    __shared__ __align__(16) float4 sqp4[256];         // packed q projections
    __shared__ __align__(16) float sv[256];            // v vector
    __shared__ float sinv[4];                          // 1/sum per query

    const int b    = blockIdx.y;
    const int q0   = blockIdx.x * 4;
    const int tid  = threadIdx.x;
    const int warp = tid >> 5;
    const int lane = tid & 31;

    // preload v + packed q projections (sqp4[d] = {q0,q1,q2,q3} at dim d)
    sv[tid] = v[tid];
    {
        float4 p;
        p.x = qp_g[(size_t)(b * TQ + q0 + 0) * DD + tid];
        p.y = qp_g[(size_t)(b * TQ + q0 + 1) * DD + tid];
        p.z = qp_g[(size_t)(b * TQ + q0 + 2) * DD + tid];
        p.w = qp_g[(size_t)(b * TQ + q0 + 3) * DD + tid];
        sqp4[tid] = p;
    }

    const float* kpT = g_kpT + (size_t)b * DD * TH;
    const int r_  = tid >> 6;            // row this thread stages (4 rows apart)
    const int c4_ = (tid & 63) << 2;     // column (float4)

    // ---- scores: s[q][t] = sum_d v[d] * tanh(qp[q][d] + kp[d][t]) ----
    float acc[4] = {0.f, 0.f, 0.f, 0.f};
    float4 pf[4];

    // prologue: chunk 0 -> buf0, prefetch chunk 1
#pragma unroll
    for (int s = 0; s < 4; s++)
        pf[s] = *(const float4*)&kpT[(size_t)(r_ + s * 4) * TH + c4_];
#pragma unroll
    for (int s = 0; s < 4; s++) *(float4*)&stage[0][r_ + s * 4][c4_] = pf[s];
#pragma unroll
    for (int s = 0; s < 4; s++)
        pf[s] = *(const float4*)&kpT[(size_t)(16 + r_ + s * 4) * TH + c4_];
    __syncthreads();

    for (int c = 0; c < 16; c++) {
        const int cur = c & 1, nxt = cur ^ 1;
        if (c < 15) {
#pragma unroll
            for (int s = 0; s < 4; s++) *(float4*)&stage[nxt][r_ + s * 4][c4_] = pf[s];
            if (c < 14) {
                const int d0n = (c + 2) * 16;
#pragma unroll
                for (int s = 0; s < 4; s++)
                    pf[s] = *(const float4*)&kpT[(size_t)(d0n + r_ + s * 4) * TH + c4_];
            }
        }
        const int d0 = c * 16;
        // v values for this chunk into registers
        float vr[16];
#pragma unroll
        for (int s = 0; s < 4; s++) {
            float4 vv = *(const float4*)&sv[d0 + s * 4];
            vr[s * 4 + 0] = vv.x; vr[s * 4 + 1] = vv.y;
            vr[s * 4 + 2] = vv.z; vr[s * 4 + 3] = vv.w;
        }
#pragma unroll
        for (int dd = 0; dd < 16; dd++) {
            float4 qv = sqp4[d0 + dd];        // LDS.128 broadcast
            float x  = stage[cur][dd][tid];   // conflict-free
            acc[0] = fmaf(vr[dd], tanh_fast(qv.x + x), acc[0]);
            acc[1] = fmaf(vr[dd], tanh_fast(qv.y + x), acc[1]);
            acc[2] = fmaf(vr[dd], tanh_fast(qv.z + x), acc[2]);
            acc[3] = fmaf(vr[dd], tanh_fast(qv.w + x), acc[3]);
        }
        __syncthreads();
    }
#pragma unroll
    for (int q = 0; q < 4; q++) sc[q][tid] = acc[q];
    __syncthreads();

    // ---- softmax (unnormalized): warps 0-3, one query each ----
    if (warp < 4) {
        float ls[8];
        float m = -1e30f;
#pragma unroll
        for (int j = 0; j < 8; j++) {
            ls[j] = sc[warp][j * 32 + lane];
            m = fmaxf(m, ls[j]);
        }
#pragma unroll
        for (int o = 16; o; o >>= 1) m = fmaxf(m, __shfl_xor_sync(0xffffffffu, m, o));
        float ssum = 0.f;
#pragma unroll
        for (int j = 0; j < 8; j++) {
            ls[j] = __expf(ls[j] - m);
            ssum += ls[j];
        }
#pragma unroll
        for (int o = 16; o; o >>= 1) ssum += __shfl_xor_sync(0xffffffffu, ssum, o);
#pragma unroll
        for (int j = 0; j < 8; j++) sc[warp][j * 32 + lane] = ls[j];
        if (lane == 0) sinv[warp] = 1.f / ssum;
    }

    // ---- context[i] = (1/sum) * sum_t e[t] * keys[b][t][i]; i = tid ----
    float ctx[4] = {0.f, 0.f, 0.f, 0.f};
    const float* kb = keys + (size_t)b * TH * DIN;

    // prologue: chunk 0 -> buf0, prefetch chunk 1
#pragma unroll
    for (int s = 0; s < 4; s++)
        pf[s] = *(const float4*)&kb[(size_t)(r_ + s * 4) * DIN + c4_];
    __syncthreads();   // also orders softmax writes (sc, sinv) for all warps
#pragma unroll
    for (int s = 0; s < 4; s++) *(float4*)&stage[0][r_ + s * 4][c4_] = pf[s];
#pragma unroll
    for (int s = 0; s < 4; s++)
        pf[s] = *(const float4*)&kb[(size_t)(16 + r_ + s * 4) * DIN + c4_];
    __syncthreads();

    for (int c = 0; c < 16; c++) {
        const int cur = c & 1, nxt = cur ^ 1;
        if (c < 15) {
#pragma unroll
            for (int s = 0; s < 4; s++) *(float4*)&stage[nxt][r_ + s * 4][c4_] = pf[s];
            if (c < 14) {
                const int t0n = (c + 2) * 16;
#pragma unroll
                for (int s = 0; s < 4; s++)
                    pf[s] = *(const float4*)&kb[(size_t)(t0n + r_ + s * 4) * DIN + c4_];
            }
        }
        const int t0 = c * 16;
#pragma unroll
        for (int tg = 0; tg < 4; tg++) {
            float kv0 = stage[cur][tg * 4 + 0][tid];
            float kv1 = stage[cur][tg * 4 + 1][tid];
            float kv2 = stage[cur][tg * 4 + 2][tid];
            float kv3 = stage[cur][tg * 4 + 3][tid];
#pragma unroll
            for (int q = 0; q < 4; q++) {
                float4 a = *(const float4*)&sc[q][t0 + tg * 4];  // broadcast
                ctx[q] = fmaf(a.x, kv0,
                         fmaf(a.y, kv1,
                         fmaf(a.z, kv2,
                         fmaf(a.w, kv3, ctx[q]))));
            }
        }
        __syncthreads();
    }

#pragma unroll
    for (int q = 0; q < 4; q++)
        out[(size_t)(b * TQ + q0 + q) * DIN + tid] = ctx[q] * sinv[q];
}

// ---------------------------------------------------------------------------
// Launch. Inputs (metadata order): inputs, state, w1, w2, v, batch_size.
// Output: (B*TQ, DIN) float32.
// ---------------------------------------------------------------------------
extern "C" void kernel_launch(void* const* d_in, const int* in_sizes, int n_in,
                              void* d_out, int out_size)
{
    const float* inputs = (const float*)d_in[0];
    const float* state  = (const float*)d_in[1];
    const float* w1     = (const float*)d_in[2];
    const float* w2     = (const float*)d_in[3];
    const float* v      = (const float*)d_in[4];
    float* out = (float*)d_out;
    (void)in_sizes; (void)n_in; (void)out_size;

    dim3 g1(128 + 32, 4);      // 160 M-tiles x 4 N-tiles, 256 threads
    proj_gemm<<<g1, 256>>>(inputs, state, w1, w2);

    float* qp_ptr;
    cudaGetSymbolAddress((void**)&qp_ptr, g_qp);

    dim3 g2(TQ / 4, B_);       // (16, 32) = 512 blocks, 4 queries each
    attn_kernel<<<g2, 256>>>(inputs, v, qp_ptr, out);
}

// round 7
// speedup vs baseline: 1.0027x; 1.0027x over previous
#include <cuda_runtime.h>

// Problem constants
#define B_    32
#define TH    256
#define TQ    64
#define DIN   256
#define DD    256   // internal dim
#define KD    256   // reduction dim of projections

typedef unsigned long long u64;

// Scratch (allocation-free rule: __device__ globals)
__device__ float g_kpT[B_ * DD * TH];  // 8 MB, TRANSPOSED: [b][d][t]
__device__ float g_qp [B_ * TQ * DD];  // 2 MB, [b*TQ+q][d]

__device__ __forceinline__ float tanh_fast(float x) {
    float y;
    asm("tanh.approx.f32 %0, %1;" : "=f"(y) : "f"(x));
    return y;
}

// ---- packed f32x2 helpers (sm_103a FFMA2 path; PTX-only, ptxas won't fuse) ----
__device__ __forceinline__ u64 pack2(float x, float y) {
    u64 r; asm("mov.b64 %0, {%1, %2};" : "=l"(r) : "f"(x), "f"(y)); return r;
}
__device__ __forceinline__ u64 dup2(float x) {
    u64 r; asm("mov.b64 %0, {%1, %1};" : "=l"(r) : "f"(x)); return r;
}
__device__ __forceinline__ void unpack2(u64 p, float& x, float& y) {
    asm("mov.b64 {%0, %1}, %2;" : "=f"(x), "=f"(y) : "l"(p));
}
__device__ __forceinline__ u64 ffma2(u64 a, u64 b, u64 c) {
    u64 d; asm("fma.rn.f32x2 %0, %1, %2, %3;" : "=l"(d) : "l"(a), "l"(b), "l"(c));
    return d;
}

// ---------------------------------------------------------------------------
// Kernel 1: combined projection GEMM, FFMA2 inner loop.
//   g_kpT[b][d][t] = sum_k inputs[(b*TH+t), k] * w1[d, k]   (transposed store)
//   g_qp[(b*TQ+q), d] = sum_k state[(b*TQ+q), k] * w2[d, k]
// Accumulators packed along m: acc2[ip][j] holds rows (ty*4+2ip, ty*4+2ip+1).
// The float4 LDS of As is reinterpreted as ulonglong2 -> packed pairs free.
// ---------------------------------------------------------------------------
__global__ __launch_bounds__(256) void proj_gemm(
    const float* __restrict__ inputs, const float* __restrict__ state,
    const float* __restrict__ w1, const float* __restrict__ w2)
{
    const int PAD = 68;
    __shared__ __align__(16) float As[16 * PAD];
    __shared__ __align__(16) float Bs[16 * PAD];

    const bool is_kp = (blockIdx.x < 128);
    const float* A;
    const float* W;
    int m0;
    if (is_kp) { A = inputs; W = w1; m0 = blockIdx.x * 64; }
    else       { A = state;  W = w2; m0 = (blockIdx.x - 128) * 64; }

    const int n0  = blockIdx.y * 64;
    const int tid = threadIdx.x;
    const int ty  = tid & 15;
    const int tx  = tid >> 4;
    const int lrow = tid >> 2;
    const int lk4  = (tid & 3) << 2;

    u64 acc2[2][4];   // [m-pair][j]
#pragma unroll
    for (int i = 0; i < 2; i++)
#pragma unroll
        for (int j = 0; j < 4; j++) acc2[i][j] = 0ULL;

    for (int kt = 0; kt < KD; kt += 16) {
        float4 av = *(const float4*)&A[(size_t)(m0 + lrow) * KD + kt + lk4];
        float4 wv = *(const float4*)&W[(size_t)(n0 + lrow) * KD + kt + lk4];
        __syncthreads();
        As[(lk4 + 0) * PAD + lrow] = av.x;
        As[(lk4 + 1) * PAD + lrow] = av.y;
        As[(lk4 + 2) * PAD + lrow] = av.z;
        As[(lk4 + 3) * PAD + lrow] = av.w;
        Bs[(lk4 + 0) * PAD + lrow] = wv.x;
        Bs[(lk4 + 1) * PAD + lrow] = wv.y;
        Bs[(lk4 + 2) * PAD + lrow] = wv.z;
        Bs[(lk4 + 3) * PAD + lrow] = wv.w;
        __syncthreads();
#pragma unroll
        for (int kk = 0; kk < 16; kk++) {
            ulonglong2 aa2 = *(const ulonglong2*)&As[kk * PAD + ty * 4]; // 2 packed pairs
            float4 bb = *(const float4*)&Bs[kk * PAD + tx * 4];
            u64 b2[4] = {dup2(bb.x), dup2(bb.y), dup2(bb.z), dup2(bb.w)};
#pragma unroll
            for (int j = 0; j < 4; j++) {
                acc2[0][j] = ffma2(aa2.x, b2[j], acc2[0][j]);
                acc2[1][j] = ffma2(aa2.y, b2[j], acc2[1][j]);
            }
        }
    }

    // unpack accumulators: acc[i][j], i = m-row offset within micro-tile
    float acc[4][4];
#pragma unroll
    for (int ip = 0; ip < 2; ip++)
#pragma unroll
        for (int j = 0; j < 4; j++)
            unpack2(acc2[ip][j], acc[2 * ip][j], acc[2 * ip + 1][j]);

    if (is_kp) {
        const int b  = m0 >> 8;
        const int t0 = m0 & 255;
#pragma unroll
        for (int j = 0; j < 4; j++) {
            float4 o = make_float4(acc[0][j], acc[1][j], acc[2][j], acc[3][j]);
            *(float4*)&g_kpT[(size_t)(b * DD + n0 + tx * 4 + j) * TH + t0 + ty * 4] = o;
        }
    } else {
#pragma unroll
        for (int i = 0; i < 4; i++) {
            float4 o = make_float4(acc[i][0], acc[i][1], acc[i][2], acc[i][3]);
            *(float4*)&g_qp[(size_t)(m0 + ty * 4 + i) * DD + n0 + tx * 4] = o;
        }
    }
}

// ---------------------------------------------------------------------------
// Kernel 2: scores + softmax + context, fused. grid = (TQ/4, B) = 512 blocks,
// 256 threads, 4 queries per block. Double-buffered SMEM staging with LDG
// prefetch. Context phase uses packed FFMA2 over q-pairs.
// ---------------------------------------------------------------------------
__global__ __launch_bounds__(256) void attn_kernel(
    const float* __restrict__ keys, const float* __restrict__ v,
    const float* __restrict__ qp_g, float* __restrict__ out)
{
    __shared__ __align__(16) float stage[2][16][260];  // 33 KB ping-pong
    __shared__ __align__(16) float sc[4][256];         // scores -> exp(scores)
    __shared__ __align__(16) u64 scp[2][256];          // exp packed over q-pairs
    __shared__ __align__(16) float4 sqp4[256];         // packed q projections
    __shared__ __align__(16) float sv[256];            // v vector
    __shared__ float sinv[4];                          // 1/sum per query

    const int b    = blockIdx.y;
    const int q0   = blockIdx.x * 4;
    const int tid  = threadIdx.x;
    const int warp = tid >> 5;
    const int lane = tid & 31;

    // preload v + packed q projections (sqp4[d] = {q0,q1,q2,q3} at dim d)
    sv[tid] = v[tid];
    {
        float4 p;
        p.x = qp_g[(size_t)(b * TQ + q0 + 0) * DD + tid];
        p.y = qp_g[(size_t)(b * TQ + q0 + 1) * DD + tid];
        p.z = qp_g[(size_t)(b * TQ + q0 + 2) * DD + tid];
        p.w = qp_g[(size_t)(b * TQ + q0 + 3) * DD + tid];
        sqp4[tid] = p;
    }

    const float* kpT = g_kpT + (size_t)b * DD * TH;
    const int r_  = tid >> 6;            // row this thread stages (4 rows apart)
    const int c4_ = (tid & 63) << 2;     // column (float4)

    // ---- scores: s[q][t] = sum_d v[d] * tanh(qp[q][d] + kp[d][t]) ----
    float acc[4] = {0.f, 0.f, 0.f, 0.f};
    float4 pf[4];

    // prologue: chunk 0 -> buf0, prefetch chunk 1
#pragma unroll
    for (int s = 0; s < 4; s++)
        pf[s] = *(const float4*)&kpT[(size_t)(r_ + s * 4) * TH + c4_];
#pragma unroll
    for (int s = 0; s < 4; s++) *(float4*)&stage[0][r_ + s * 4][c4_] = pf[s];
#pragma unroll
    for (int s = 0; s < 4; s++)
        pf[s] = *(const float4*)&kpT[(size_t)(16 + r_ + s * 4) * TH + c4_];
    __syncthreads();

    for (int c = 0; c < 16; c++) {
        const int cur = c & 1, nxt = cur ^ 1;
        if (c < 15) {
#pragma unroll
            for (int s = 0; s < 4; s++) *(float4*)&stage[nxt][r_ + s * 4][c4_] = pf[s];
            if (c < 14) {
                const int d0n = (c + 2) * 16;
#pragma unroll
                for (int s = 0; s < 4; s++)
                    pf[s] = *(const float4*)&kpT[(size_t)(d0n + r_ + s * 4) * TH + c4_];
            }
        }
        const int d0 = c * 16;
        float vr[16];
#pragma unroll
        for (int s = 0; s < 4; s++) {
            float4 vv = *(const float4*)&sv[d0 + s * 4];
            vr[s * 4 + 0] = vv.x; vr[s * 4 + 1] = vv.y;
            vr[s * 4 + 2] = vv.z; vr[s * 4 + 3] = vv.w;
        }
#pragma unroll
        for (int dd = 0; dd < 16; dd++) {
            float4 qv = sqp4[d0 + dd];        // LDS.128 broadcast
            float x  = stage[cur][dd][tid];   // conflict-free
            acc[0] = fmaf(vr[dd], tanh_fast(qv.x + x), acc[0]);
            acc[1] = fmaf(vr[dd], tanh_fast(qv.y + x), acc[1]);
            acc[2] = fmaf(vr[dd], tanh_fast(qv.z + x), acc[2]);
            acc[3] = fmaf(vr[dd], tanh_fast(qv.w + x), acc[3]);
        }
        __syncthreads();
    }
#pragma unroll
    for (int q = 0; q < 4; q++) sc[q][tid] = acc[q];
    __syncthreads();

    // ---- softmax (unnormalized): warps 0-3, one query each ----
    if (warp < 4) {
        float ls[8];
        float m = -1e30f;
#pragma unroll
        for (int j = 0; j < 8; j++) {
            ls[j] = sc[warp][j * 32 + lane];
            m = fmaxf(m, ls[j]);
        }
#pragma unroll
        for (int o = 16; o; o >>= 1) m = fmaxf(m, __shfl_xor_sync(0xffffffffu, m, o));
        float ssum = 0.f;
#pragma unroll
        for (int j = 0; j < 8; j++) {
            ls[j] = __expf(ls[j] - m);
            ssum += ls[j];
        }
#pragma unroll
        for (int o = 16; o; o >>= 1) ssum += __shfl_xor_sync(0xffffffffu, ssum, o);
#pragma unroll
        for (int j = 0; j < 8; j++) sc[warp][j * 32 + lane] = ls[j];
        if (lane == 0) sinv[warp] = 1.f / ssum;
    }
    __syncthreads();

    // pack exp-weights over q-pairs: scp[p][t] = {e[2p][t], e[2p+1][t]}
    scp[0][tid] = pack2(sc[0][tid], sc[1][tid]);
    scp[1][tid] = pack2(sc[2][tid], sc[3][tid]);

    // ---- context[i] = (1/sum) * sum_t e[t] * keys[b][t][i]; i = tid ----
    u64 ctx2[2] = {0ULL, 0ULL};          // {q0,q1}, {q2,q3}
    const float* kb = keys + (size_t)b * TH * DIN;

    // prologue: chunk 0 -> buf0, prefetch chunk 1
#pragma unroll
    for (int s = 0; s < 4; s++)
        pf[s] = *(const float4*)&kb[(size_t)(r_ + s * 4) * DIN + c4_];
    __syncthreads();   // orders scp writes for all warps
#pragma unroll
    for (int s = 0; s < 4; s++) *(float4*)&stage[0][r_ + s * 4][c4_] = pf[s];
#pragma unroll
    for (int s = 0; s < 4; s++)
        pf[s] = *(const float4*)&kb[(size_t)(16 + r_ + s * 4) * DIN + c4_];
    __syncthreads();

    for (int c = 0; c < 16; c++) {
        const int cur = c & 1, nxt = cur ^ 1;
        if (c < 15) {
#pragma unroll
            for (int s = 0; s < 4; s++) *(float4*)&stage[nxt][r_ + s * 4][c4_] = pf[s];
            if (c < 14) {
                const int t0n = (c + 2) * 16;
#pragma unroll
                for (int s = 0; s < 4; s++)
                    pf[s] = *(const float4*)&kb[(size_t)(t0n + r_ + s * 4) * DIN + c4_];
            }
        }
        const int t0 = c * 16;
#pragma unroll
        for (int tt = 0; tt < 16; tt++) {
            u64 kv2 = dup2(stage[cur][tt][tid]);
            ctx2[0] = ffma2(scp[0][t0 + tt], kv2, ctx2[0]);   // LDS.64 broadcast
            ctx2[1] = ffma2(scp[1][t0 + tt], kv2, ctx2[1]);
        }
        __syncthreads();
    }

    float c0, c1, c2, c3;
    unpack2(ctx2[0], c0, c1);
    unpack2(ctx2[1], c2, c3);
    out[(size_t)(b * TQ + q0 + 0) * DIN + tid] = c0 * sinv[0];
    out[(size_t)(b * TQ + q0 + 1) * DIN + tid] = c1 * sinv[1];
    out[(size_t)(b * TQ + q0 + 2) * DIN + tid] = c2 * sinv[2];
    out[(size_t)(b * TQ + q0 + 3) * DIN + tid] = c3 * sinv[3];
}

// ---------------------------------------------------------------------------
// Launch. Inputs (metadata order): inputs, state, w1, w2, v, batch_size.
// Output: (B*TQ, DIN) float32.
// ---------------------------------------------------------------------------
extern "C" void kernel_launch(void* const* d_in, const int* in_sizes, int n_in,
                              void* d_out, int out_size)
{
    const float* inputs = (const float*)d_in[0];
    const float* state  = (const float*)d_in[1];
    const float* w1     = (const float*)d_in[2];
    const float* w2     = (const float*)d_in[3];
    const float* v      = (const float*)d_in[4];
    float* out = (float*)d_out;
    (void)in_sizes; (void)n_in; (void)out_size;

    dim3 g1(128 + 32, 4);      // 160 M-tiles x 4 N-tiles, 256 threads
    proj_gemm<<<g1, 256>>>(inputs, state, w1, w2);

    float* qp_ptr;
    cudaGetSymbolAddress((void**)&qp_ptr, g_qp);

    dim3 g2(TQ / 4, B_);       // (16, 32) = 512 blocks, 4 queries each
    attn_kernel<<<g2, 256>>>(inputs, v, qp_ptr, out);
}

// round 8
// speedup vs baseline: 1.0251x; 1.0223x over previous
#include <cuda_runtime.h>

// Problem constants
#define B_    32
#define TH    256
#define TQ    64
#define DIN   256
#define DD    256   // internal dim
#define KD    256   // reduction dim of projections

typedef unsigned long long u64;

// Scratch (allocation-free rule: __device__ globals)
__device__ float g_kpT[B_ * DD * TH];  // 8 MB, TRANSPOSED: [b][d][t]
__device__ float g_qp [B_ * TQ * DD];  // 2 MB, [b*TQ+q][d]

__device__ __forceinline__ float tanh_fast(float x) {
    float y;
    asm("tanh.approx.f32 %0, %1;" : "=f"(y) : "f"(x));
    return y;
}

// ---- packed f32x2 helpers (sm_103a FFMA2; PTX-only, ptxas won't fuse) ----
__device__ __forceinline__ u64 dup2(float x) {
    u64 r; asm("mov.b64 %0, {%1, %1};" : "=l"(r) : "f"(x)); return r;
}
__device__ __forceinline__ void unpack2(u64 p, float& x, float& y) {
    asm("mov.b64 {%0, %1}, %2;" : "=f"(x), "=f"(y) : "l"(p));
}
__device__ __forceinline__ u64 ffma2(u64 a, u64 b, u64 c) {
    u64 d; asm("fma.rn.f32x2 %0, %1, %2, %3;" : "=l"(d) : "l"(a), "l"(b), "l"(c));
    return d;
}

// ---------------------------------------------------------------------------
// Kernel 1: combined projection GEMM, FFMA2 inner loop + double-buffered SMEM
// with 2-chunk-ahead LDG prefetch (1 barrier per K-chunk).
//   g_kpT[b][d][t] = sum_k inputs[(b*TH+t), k] * w1[d, k]   (transposed store)
//   g_qp[(b*TQ+q), d] = sum_k state[(b*TQ+q), k] * w2[d, k]
// ---------------------------------------------------------------------------
__global__ __launch_bounds__(256) void proj_gemm(
    const float* __restrict__ inputs, const float* __restrict__ state,
    const float* __restrict__ w1, const float* __restrict__ w2)
{
    const int PAD = 68;
    __shared__ __align__(16) float As[2][16 * PAD];
    __shared__ __align__(16) float Bs[2][16 * PAD];

    const bool is_kp = (blockIdx.x < 128);
    const float* A;
    const float* W;
    int m0;
    if (is_kp) { A = inputs; W = w1; m0 = blockIdx.x * 64; }
    else       { A = state;  W = w2; m0 = (blockIdx.x - 128) * 64; }

    const int n0  = blockIdx.y * 64;
    const int tid = threadIdx.x;
    const int ty  = tid & 15;
    const int tx  = tid >> 4;
    const int lrow = tid >> 2;
    const int lk4  = (tid & 3) << 2;

    const float* pa = &A[(size_t)(m0 + lrow) * KD + lk4];
    const float* pw = &W[(size_t)(n0 + lrow) * KD + lk4];

    u64 acc2[2][4];   // [m-pair][j]
#pragma unroll
    for (int i = 0; i < 2; i++)
#pragma unroll
        for (int j = 0; j < 4; j++) acc2[i][j] = 0ULL;

    float4 av, wv;

    // prologue: chunk 0 -> buf0; prefetch chunk 1
    av = *(const float4*)&pa[0];
    wv = *(const float4*)&pw[0];
    {
        float* as = As[0]; float* bs = Bs[0];
        as[(lk4 + 0) * PAD + lrow] = av.x;
        as[(lk4 + 1) * PAD + lrow] = av.y;
        as[(lk4 + 2) * PAD + lrow] = av.z;
        as[(lk4 + 3) * PAD + lrow] = av.w;
        bs[(lk4 + 0) * PAD + lrow] = wv.x;
        bs[(lk4 + 1) * PAD + lrow] = wv.y;
        bs[(lk4 + 2) * PAD + lrow] = wv.z;
        bs[(lk4 + 3) * PAD + lrow] = wv.w;
    }
    av = *(const float4*)&pa[16];
    wv = *(const float4*)&pw[16];
    __syncthreads();

    for (int c = 0; c < 16; c++) {
        const int cur = c & 1, nxt = cur ^ 1;
        if (c < 15) {
            float* as = As[nxt]; float* bs = Bs[nxt];
            as[(lk4 + 0) * PAD + lrow] = av.x;
            as[(lk4 + 1) * PAD + lrow] = av.y;
            as[(lk4 + 2) * PAD + lrow] = av.z;
            as[(lk4 + 3) * PAD + lrow] = av.w;
            bs[(lk4 + 0) * PAD + lrow] = wv.x;
            bs[(lk4 + 1) * PAD + lrow] = wv.y;
            bs[(lk4 + 2) * PAD + lrow] = wv.z;
            bs[(lk4 + 3) * PAD + lrow] = wv.w;
            if (c < 14) {
                av = *(const float4*)&pa[(c + 2) * 16];
                wv = *(const float4*)&pw[(c + 2) * 16];
            }
        }
        const float* as = As[cur];
        const float* bs = Bs[cur];
#pragma unroll
        for (int kk = 0; kk < 16; kk++) {
            ulonglong2 aa2 = *(const ulonglong2*)&as[kk * PAD + ty * 4];
            float4 bb = *(const float4*)&bs[kk * PAD + tx * 4];
            u64 b2[4] = {dup2(bb.x), dup2(bb.y), dup2(bb.z), dup2(bb.w)};
#pragma unroll
            for (int j = 0; j < 4; j++) {
                acc2[0][j] = ffma2(aa2.x, b2[j], acc2[0][j]);
                acc2[1][j] = ffma2(aa2.y, b2[j], acc2[1][j]);
            }
        }
        __syncthreads();
    }

    float acc[4][4];
#pragma unroll
    for (int ip = 0; ip < 2; ip++)
#pragma unroll
        for (int j = 0; j < 4; j++)
            unpack2(acc2[ip][j], acc[2 * ip][j], acc[2 * ip + 1][j]);

    if (is_kp) {
        const int b  = m0 >> 8;
        const int t0 = m0 & 255;
#pragma unroll
        for (int j = 0; j < 4; j++) {
            float4 o = make_float4(acc[0][j], acc[1][j], acc[2][j], acc[3][j]);
            *(float4*)&g_kpT[(size_t)(b * DD + n0 + tx * 4 + j) * TH + t0 + ty * 4] = o;
        }
    } else {
#pragma unroll
        for (int i = 0; i < 4; i++) {
            float4 o = make_float4(acc[i][0], acc[i][1], acc[i][2], acc[i][3]);
            *(float4*)&g_qp[(size_t)(m0 + ty * 4 + i) * DD + n0 + tx * 4] = o;
        }
    }
}

// ---------------------------------------------------------------------------
// Kernel 2: scores + softmax + context, fused. grid = (TQ/4, B) = 512 blocks,
// 256 threads, 4 queries per block. Double-buffered SMEM staging with LDG
// prefetch (1 barrier per chunk). Context phase: scalar FMA with float4
// alpha broadcasts (R5 form — lowest LDS pressure).
// ---------------------------------------------------------------------------
__global__ __launch_bounds__(256) void attn_kernel(
    const float* __restrict__ keys, const float* __restrict__ v,
    const float* __restrict__ qp_g, float* __restrict__ out)
{
    __shared__ __align__(16) float stage[2][16][260];  // 33 KB ping-pong
    __shared__ __align__(16) float sc[4][256];         // scores -> exp(scores)
    __shared__ __align__(16) float4 sqp4[256];         // packed q projections
    __shared__ __align__(16) float sv[256];            // v vector
    __shared__ float sinv[4];                          // 1/sum per query

    const int b    = blockIdx.y;
    const int q0   = blockIdx.x * 4;
    const int tid  = threadIdx.x;
    const int warp = tid >> 5;
    const int lane = tid & 31;

    // preload v + packed q projections (sqp4[d] = {q0,q1,q2,q3} at dim d)
    sv[tid] = v[tid];
    {
        float4 p;
        p.x = qp_g[(size_t)(b * TQ + q0 + 0) * DD + tid];
        p.y = qp_g[(size_t)(b * TQ + q0 + 1) * DD + tid];
        p.z = qp_g[(size_t)(b * TQ + q0 + 2) * DD + tid];
        p.w = qp_g[(size_t)(b * TQ + q0 + 3) * DD + tid];
        sqp4[tid] = p;
    }

    const float* kpT = g_kpT + (size_t)b * DD * TH;
    const int r_  = tid >> 6;            // row this thread stages (4 rows apart)
    const int c4_ = (tid & 63) << 2;     // column (float4)

    // ---- scores: s[q][t] = sum_d v[d] * tanh(qp[q][d] + kp[d][t]) ----
    float acc[4] = {0.f, 0.f, 0.f, 0.f};
    float4 pf[4];

    // prologue: chunk 0 -> buf0, prefetch chunk 1
#pragma unroll
    for (int s = 0; s < 4; s++)
        pf[s] = *(const float4*)&kpT[(size_t)(r_ + s * 4) * TH + c4_];
#pragma unroll
    for (int s = 0; s < 4; s++) *(float4*)&stage[0][r_ + s * 4][c4_] = pf[s];
#pragma unroll
    for (int s = 0; s < 4; s++)
        pf[s] = *(const float4*)&kpT[(size_t)(16 + r_ + s * 4) * TH + c4_];
    __syncthreads();

    for (int c = 0; c < 16; c++) {
        const int cur = c & 1, nxt = cur ^ 1;
        if (c < 15) {
#pragma unroll
            for (int s = 0; s < 4; s++) *(float4*)&stage[nxt][r_ + s * 4][c4_] = pf[s];
            if (c < 14) {
                const int d0n = (c + 2) * 16;
#pragma unroll
                for (int s = 0; s < 4; s++)
                    pf[s] = *(const float4*)&kpT[(size_t)(d0n + r_ + s * 4) * TH + c4_];
            }
        }
        const int d0 = c * 16;
        float vr[16];
#pragma unroll
        for (int s = 0; s < 4; s++) {
            float4 vv = *(const float4*)&sv[d0 + s * 4];
            vr[s * 4 + 0] = vv.x; vr[s * 4 + 1] = vv.y;
            vr[s * 4 + 2] = vv.z; vr[s * 4 + 3] = vv.w;
        }
#pragma unroll
        for (int dd = 0; dd < 16; dd++) {
            float4 qv = sqp4[d0 + dd];        // LDS.128 broadcast
            float x  = stage[cur][dd][tid];   // conflict-free
            acc[0] = fmaf(vr[dd], tanh_fast(qv.x + x), acc[0]);
            acc[1] = fmaf(vr[dd], tanh_fast(qv.y + x), acc[1]);
            acc[2] = fmaf(vr[dd], tanh_fast(qv.z + x), acc[2]);
            acc[3] = fmaf(vr[dd], tanh_fast(qv.w + x), acc[3]);
        }
        __syncthreads();
    }
#pragma unroll
    for (int q = 0; q < 4; q++) sc[q][tid] = acc[q];
    __syncthreads();

    // ---- softmax (unnormalized): warps 0-3, one query each ----
    if (warp < 4) {
        float ls[8];
        float m = -1e30f;
#pragma unroll
        for (int j = 0; j < 8; j++) {
            ls[j] = sc[warp][j * 32 + lane];
            m = fmaxf(m, ls[j]);
        }
#pragma unroll
        for (int o = 16; o; o >>= 1) m = fmaxf(m, __shfl_xor_sync(0xffffffffu, m, o));
        float ssum = 0.f;
#pragma unroll
        for (int j = 0; j < 8; j++) {
            ls[j] = __expf(ls[j] - m);
            ssum += ls[j];
        }
#pragma unroll
        for (int o = 16; o; o >>= 1) ssum += __shfl_xor_sync(0xffffffffu, ssum, o);
#pragma unroll
        for (int j = 0; j < 8; j++) sc[warp][j * 32 + lane] = ls[j];
        if (lane == 0) sinv[warp] = 1.f / ssum;
    }

    // ---- context[i] = (1/sum) * sum_t e[t] * keys[b][t][i]; i = tid ----
    float ctx[4] = {0.f, 0.f, 0.f, 0.f};
    const float* kb = keys + (size_t)b * TH * DIN;

    // prologue: chunk 0 -> buf0, prefetch chunk 1
#pragma unroll
    for (int s = 0; s < 4; s++)
        pf[s] = *(const float4*)&kb[(size_t)(r_ + s * 4) * DIN + c4_];
    __syncthreads();   // orders softmax writes (sc, sinv) for all warps
#pragma unroll
    for (int s = 0; s < 4; s++) *(float4*)&stage[0][r_ + s * 4][c4_] = pf[s];
#pragma unroll
    for (int s = 0; s < 4; s++)
        pf[s] = *(const float4*)&kb[(size_t)(16 + r_ + s * 4) * DIN + c4_];
    __syncthreads();

    for (int c = 0; c < 16; c++) {
        const int cur = c & 1, nxt = cur ^ 1;
        if (c < 15) {
#pragma unroll
            for (int s = 0; s < 4; s++) *(float4*)&stage[nxt][r_ + s * 4][c4_] = pf[s];
            if (c < 14) {
                const int t0n = (c + 2) * 16;
#pragma unroll
                for (int s = 0; s < 4; s++)
                    pf[s] = *(const float4*)&kb[(size_t)(t0n + r_ + s * 4) * DIN + c4_];
            }
        }
        const int t0 = c * 16;
#pragma unroll
        for (int tg = 0; tg < 4; tg++) {
            float kv0 = stage[cur][tg * 4 + 0][tid];
            float kv1 = stage[cur][tg * 4 + 1][tid];
            float kv2 = stage[cur][tg * 4 + 2][tid];
            float kv3 = stage[cur][tg * 4 + 3][tid];
#pragma unroll
            for (int q = 0; q < 4; q++) {
                float4 a = *(const float4*)&sc[q][t0 + tg * 4];  // broadcast
                ctx[q] = fmaf(a.x, kv0,
                         fmaf(a.y, kv1,
                         fmaf(a.z, kv2,
                         fmaf(a.w, kv3, ctx[q]))));
            }
        }
        __syncthreads();
    }

#pragma unroll
    for (int q = 0; q < 4; q++)
        out[(size_t)(b * TQ + q0 + q) * DIN + tid] = ctx[q] * sinv[q];
}

// ---------------------------------------------------------------------------
// Launch. Inputs (metadata order): inputs, state, w1, w2, v, batch_size.
// Output: (B*TQ, DIN) float32.
// ---------------------------------------------------------------------------
extern "C" void kernel_launch(void* const* d_in, const int* in_sizes, int n_in,
                              void* d_out, int out_size)
{
    const float* inputs = (const float*)d_in[0];
    const float* state  = (const float*)d_in[1];
    const float* w1     = (const float*)d_in[2];
    const float* w2     = (const float*)d_in[3];
    const float* v      = (const float*)d_in[4];
    float* out = (float*)d_out;
    (void)in_sizes; (void)n_in; (void)out_size;

    dim3 g1(128 + 32, 4);      // 160 M-tiles x 4 N-tiles, 256 threads
    proj_gemm<<<g1, 256>>>(inputs, state, w1, w2);

    float* qp_ptr;
    cudaGetSymbolAddress((void**)&qp_ptr, g_qp);

    dim3 g2(TQ / 4, B_);       // (16, 32) = 512 blocks, 4 queries each
    attn_kernel<<<g2, 256>>>(inputs, v, qp_ptr, out);
}